// round 1
// baseline (speedup 1.0000x reference)
#include <cuda_runtime.h>
#include <math.h>

#define N_OBS   256
#define N_Y     128
#define N_X     64
#define NITERS  150
#define EPT_STRIDE 260   // padded: conflict-free float4 LDS across warp rows

// Device scratch (allocation-free rule: __device__ globals)
__device__ float g_epT[N_Y * N_OBS];            // ep transposed [j][t]
__device__ float g_yhat_fallback[N_OBS * N_Y];  // used only if out buffer lacks Y_hat space

struct SolverSmem {
    float epT[N_Y * EPT_STRIDE];  // 133120 B
    float z[N_Y];
    float yhat[N_Y];
    float w[N_OBS];
    float part[N_OBS];
    float sortbuf[N_Y];
    float css[N_Y];
    float v[N_Y];
    float red1[8];
    float red2[8];
    int   cnt[4];
    float c, eta, lam, theta;
};

// ---------------------------------------------------------------------------
// Kernel 1: Y_hat = X @ W^T + b ; epT = (Y - Y_hat)^T
// grid = 256 blocks (one per observation t), 128 threads (one per output j)
// ---------------------------------------------------------------------------
__global__ void prep_kernel(const float* __restrict__ X,
                            const float* __restrict__ Y,
                            const float* __restrict__ W,
                            const float* __restrict__ b,
                            float* __restrict__ yhat_out) {
    __shared__ float Xs[N_X];
    __shared__ float Ws[N_Y * (N_X + 1)];   // padded to kill bank conflicts
    const int t = blockIdx.x;
    const int i = threadIdx.x;

    if (i < N_X) Xs[i] = X[t * N_X + i];
    for (int idx = i; idx < N_Y * N_X; idx += blockDim.x) {
        int r = idx >> 6, cx = idx & 63;
        Ws[r * (N_X + 1) + cx] = W[idx];
    }
    __syncthreads();

    float acc = b[i];
#pragma unroll
    for (int x = 0; x < N_X; x++) acc += Xs[x] * Ws[i * (N_X + 1) + x];

    yhat_out[t * N_Y + i] = acc;
    g_epT[i * N_OBS + t] = Y[t * N_Y + i] - acc;
}

// ---------------------------------------------------------------------------
// Kernel 2: one CTA per scenario; 150 projected-subgradient iterations.
// ---------------------------------------------------------------------------
__global__ __launch_bounds__(256, 1)
void solver_kernel(const float* __restrict__ yhat_all,
                   const float* __restrict__ delta_p,
                   const float* __restrict__ gamma_p,
                   float* __restrict__ zout) {
    extern __shared__ char smem_raw[];
    SolverSmem* S = reinterpret_cast<SolverSmem*>(smem_raw);

    const int tid  = threadIdx.x;
    const int scen = blockIdx.x;
    const float delta = *delta_p;
    const float gamma = *gamma_p;

    // Load epT (global [j][t] layout) into padded shared
    for (int idx = tid; idx < N_Y * N_OBS; idx += 256) {
        int j = idx >> 8;          // / 256
        int t = idx & 255;
        S->epT[j * EPT_STRIDE + t] = g_epT[idx];
    }
    if (tid < N_Y) {
        S->z[tid]    = 1.0f / (float)N_Y;
        S->yhat[tid] = yhat_all[scen * N_Y + tid];
    }
    if (tid == 0) { S->c = 0.0f; S->eta = 0.0f; S->lam = 0.1f; }
    __syncthreads();

    // Thread t caches ep row t in registers: ep[t][j] = epT[j][t]
    float ep_r[N_Y];
#pragma unroll
    for (int j = 0; j < N_Y; j++) ep_r[j] = S->epT[j * EPT_STRIDE + tid];

    for (int k = 0; k < NITERS; k++) {
        const float lr = 0.05f / sqrtf(1.0f + (float)k);
        const float c = S->c, eta = S->eta, lam = S->lam;

        // ---- Phase A: r_t = ep_t . z - c  (register FMAs, z broadcast) ----
        float r = -c;
        const float4* z4 = reinterpret_cast<const float4*>(S->z);
#pragma unroll
        for (int q = 0; q < N_Y / 4; q++) {
            float4 zv = z4[q];
            r += ep_r[4 * q + 0] * zv.x;
            r += ep_r[4 * q + 1] * zv.y;
            r += ep_r[4 * q + 2] * zv.z;
            r += ep_r[4 * q + 3] * zv.w;
        }

        // ---- Indicator, weights, scalar-gradient reductions ----
        const float a = r * r - eta;
        float I;
        if (a > -lam)      I = 1.0f;
        else if (a < -lam) I = 0.0f;
        else               I = 0.5f;   // JAX balanced max-grad on ties
        const float w = I * 2.0f * r * (1.0f / (float)N_OBS);
        S->w[tid] = w;

        float sI = I, sw = w;
#pragma unroll
        for (int off = 16; off > 0; off >>= 1) {
            sI += __shfl_down_sync(0xffffffffu, sI, off);
            sw += __shfl_down_sync(0xffffffffu, sw, off);
        }
        if ((tid & 31) == 0) { S->red1[tid >> 5] = sI; S->red2[tid >> 5] = sw; }
        __syncthreads();

        if (tid == 0) {
            float SI = 0.0f, SW = 0.0f;
#pragma unroll
            for (int i = 0; i < 8; i++) { SI += S->red1[i]; SW += S->red2[i]; }
            const float g_c   = -SW;
            const float g_eta = 1.0f - SI * (1.0f / (float)N_OBS);
            const float g_lam = delta - 1.0f + SI * (1.0f / (float)N_OBS);
            S->c   = c - lr * g_c;
            S->eta = eta - lr * g_eta;
            S->lam = fmaxf(lam - lr * g_lam, 0.0f);
        }

        // ---- Phase B: g_z[j] = sum_t w_t * epT[j][t]  (split over t-halves) ----
        {
            const int j = tid & 127;
            const int tbase = (tid >> 7) << 7;   // 0 or 128
            const float4* row = reinterpret_cast<const float4*>(&S->epT[j * EPT_STRIDE + tbase]);
            const float4* wv  = reinterpret_cast<const float4*>(&S->w[tbase]);
            float acc = 0.0f;
#pragma unroll
            for (int q = 0; q < 32; q++) {
                float4 e = row[q];
                float4 ww = wv[q];
                acc += e.x * ww.x + e.y * ww.y + e.z * ww.z + e.w * ww.w;
            }
            S->part[tid] = acc;
        }
        __syncthreads();

        if (tid < N_Y) {
            const float gz = S->part[tid] + S->part[tid + 128] - gamma * S->yhat[tid];
            const float v = S->z[tid] - lr * gz;
            S->v[tid] = v;
            S->sortbuf[tid] = v;
        }
        __syncthreads();

        // ---- Simplex projection: bitonic ascending sort of 128 values ----
        for (int kk = 2; kk <= 128; kk <<= 1) {
            for (int jj = kk >> 1; jj > 0; jj >>= 1) {
                if (tid < 128) {
                    const int ixj = tid ^ jj;
                    if (ixj > tid) {
                        const float x0 = S->sortbuf[tid];
                        const float x1 = S->sortbuf[ixj];
                        const bool up = ((tid & kk) == 0);
                        if ((x0 > x1) == up) { S->sortbuf[tid] = x1; S->sortbuf[ixj] = x0; }
                    }
                }
                __syncthreads();
            }
        }

        // css[i] = inclusive cumsum of descending-sorted u
        if (tid < 128) S->css[tid] = S->sortbuf[127 - tid];
        __syncthreads();
        for (int d = 1; d < 128; d <<= 1) {
            float add = 0.0f;
            if (tid < 128 && tid >= d) add = S->css[tid - d];
            __syncthreads();
            if (tid < 128) S->css[tid] += add;
            __syncthreads();
        }

        // rho = #{ u_i + (1 - css_i)/(i+1) > 0 }, theta = (css[rho-1]-1)/rho
        if (tid < 128) {
            const float u = S->sortbuf[127 - tid];
            const bool cond = (u + (1.0f - S->css[tid]) / (float)(tid + 1)) > 0.0f;
            const unsigned bal = __ballot_sync(0xffffffffu, cond);
            if ((tid & 31) == 0) S->cnt[tid >> 5] = __popc(bal);
        }
        __syncthreads();
        if (tid == 0) {
            const int rho = S->cnt[0] + S->cnt[1] + S->cnt[2] + S->cnt[3];
            S->theta = (S->css[rho - 1] - 1.0f) / (float)rho;
        }
        __syncthreads();
        if (tid < 128) S->z[tid] = fmaxf(S->v[tid] - S->theta, 0.0f);
        __syncthreads();
    }

    if (tid < N_Y) zout[scen * N_Y + tid] = S->z[tid];
}

// ---------------------------------------------------------------------------
extern "C" void kernel_launch(void* const* d_in, const int* in_sizes, int n_in,
                              void* d_out, int out_size) {
    const float* X     = (const float*)d_in[0];   // (256, 64)
    const float* Y     = (const float*)d_in[1];   // (256, 128)
    const float* W     = (const float*)d_in[2];   // (128, 64)
    const float* b     = (const float*)d_in[3];   // (128,)
    const float* delta = (const float*)d_in[4];   // scalar
    const float* gamma = (const float*)d_in[5];   // scalar

    float* out = (float*)d_out;
    float* zout = out;                              // Z_star first (tuple order)
    float* yhat;
    if (out_size >= 2 * N_OBS * N_Y) {
        yhat = out + N_OBS * N_Y;                   // Y_hat second half
    } else {
        void* p = nullptr;
        cudaGetSymbolAddress(&p, g_yhat_fallback);
        yhat = (float*)p;
    }

    static const size_t smem_bytes = sizeof(SolverSmem);
    cudaFuncSetAttribute(solver_kernel,
                         cudaFuncAttributeMaxDynamicSharedMemorySize,
                         (int)smem_bytes);

    prep_kernel<<<N_OBS, N_Y>>>(X, Y, W, b, yhat);
    solver_kernel<<<N_OBS, 256, smem_bytes>>>(yhat, delta, gamma, zout);
}

// round 2
// speedup vs baseline: 2.4080x; 2.4080x over previous
#include <cuda_runtime.h>
#include <math.h>

#define N_OBS   256
#define N_Y     128
#define N_X     64
#define NITERS  150
#define EPT_STRIDE 260   // stride mod 32 = 4 -> conflict-free float4 LDS across rows

__device__ float g_epT[N_Y * N_OBS];            // ep transposed [j][t]
__device__ float g_yhat_fallback[N_OBS * N_Y];

struct SolverSmem {
    float epT[N_Y * EPT_STRIDE];                // 133120 B, shared by both scenarios
    float zA[N_Y],  zB[N_Y];
    float yhA[N_Y], yhB[N_Y];
    float wA[N_OBS], wB[N_OBS];
    float partA[N_OBS], partB[N_OBS];
    float vA[N_Y], vB[N_Y];
    float redIA[8], redWA[8], redIB[8], redWB[8];
    float cA, etaA, lamA;
    float cB, etaB, lamB;
};

// ---------------------------------------------------------------------------
// Kernel 1: Y_hat = X @ W^T + b ; epT = (Y - Y_hat)^T
// ---------------------------------------------------------------------------
__global__ void prep_kernel(const float* __restrict__ X,
                            const float* __restrict__ Y,
                            const float* __restrict__ W,
                            const float* __restrict__ b,
                            float* __restrict__ yhat_out) {
    __shared__ float Xs[N_X];
    __shared__ float Ws[N_Y * (N_X + 1)];
    const int t = blockIdx.x;
    const int i = threadIdx.x;

    if (i < N_X) Xs[i] = X[t * N_X + i];
    for (int idx = i; idx < N_Y * N_X; idx += blockDim.x) {
        int r = idx >> 6, cx = idx & 63;
        Ws[r * (N_X + 1) + cx] = W[idx];
    }
    __syncthreads();

    float acc = b[i];
#pragma unroll
    for (int x = 0; x < N_X; x++) acc += Xs[x] * Ws[i * (N_X + 1) + x];

    yhat_out[t * N_Y + i] = acc;
    g_epT[i * N_OBS + t] = Y[t * N_Y + i] - acc;
}

// ---------------------------------------------------------------------------
// Warp-local exact simplex projection of 128 values (one warp, 4 vals/lane).
// Reads v[0..127] from SMEM, writes z[j] = max(v[j] - theta, 0).
// ---------------------------------------------------------------------------
__device__ __forceinline__ void project_warp(const float* __restrict__ vv,
                                             float* __restrict__ zz) {
    const unsigned FULL = 0xffffffffu;
    const int lane = threadIdx.x & 31;

    // value index i = r*32 + lane
    float val[4];
#pragma unroll
    for (int r = 0; r < 4; r++) val[r] = vv[r * 32 + lane];

    // Bitonic ascending sort over i. Strides >=32 are register-local (same lane),
    // strides <=16 are shfl_xor.
#pragma unroll
    for (int kk = 2; kk <= 128; kk <<= 1) {
#pragma unroll
        for (int jj = kk >> 1; jj > 0; jj >>= 1) {
            if (jj >= 32) {
                const int rx = jj >> 5;   // 1 or 2
#pragma unroll
                for (int r = 0; r < 4; r++) {
                    if ((r & rx) == 0) {
                        const int r2 = r | rx;
                        const bool asc = (((r * 32) & kk) == 0);  // lane bits < bit5
                        const float a = val[r], b = val[r2];
                        const float lo = fminf(a, b), hi = fmaxf(a, b);
                        val[r]  = asc ? lo : hi;
                        val[r2] = asc ? hi : lo;
                    }
                }
            } else {
#pragma unroll
                for (int r = 0; r < 4; r++) {
                    const float pv = __shfl_xor_sync(FULL, val[r], jj);
                    const bool asc   = (((r * 32 + lane) & kk) == 0);
                    const bool lower = ((lane & jj) == 0);
                    val[r] = (lower == asc) ? fminf(val[r], pv) : fmaxf(val[r], pv);
                }
            }
        }
    }

    // Inclusive prefix sum P[i] over ascending-sorted values.
    float P[4];
    float off = 0.0f;
#pragma unroll
    for (int r = 0; r < 4; r++) {
        float x = val[r];
#pragma unroll
        for (int d = 1; d < 32; d <<= 1) {
            const float y = __shfl_up_sync(FULL, x, d);
            if (lane >= d) x += y;
        }
        P[r] = x + off;
        off += __shfl_sync(FULL, x, 31);
    }
    const float Stot = off;

    // Descending cumsum at position i (idx = 127 - i): css = Stot - P[i] + u[i].
    // cond[idx] = u_desc[idx] + (1 - css[idx]) / (idx+1) > 0, idx+1 = 128 - i.
    int rho = 0;
    float cssr[4];
#pragma unroll
    for (int r = 0; r < 4; r++) {
        const int i = r * 32 + lane;
        const float css = Stot - P[r] + val[r];
        cssr[r] = css;
        const bool cond = (val[r] + (1.0f - css) / (float)(128 - i)) > 0.0f;
        rho += __popc(__ballot_sync(FULL, cond));
    }

    // theta = (css[rho-1] - 1) / rho ; css[rho-1] lives at i = 128 - rho.
    const int it = 128 - rho;
    const int rt = it >> 5, lt = it & 31;
    const float sel = (rt == 0) ? cssr[0] : (rt == 1) ? cssr[1]
                    : (rt == 2) ? cssr[2] : cssr[3];
    const float css_t = __shfl_sync(FULL, sel, lt);
    const float theta = (css_t - 1.0f) / (float)rho;

#pragma unroll
    for (int r = 0; r < 4; r++) {
        const int j = r * 32 + lane;
        zz[j] = fmaxf(vv[j] - theta, 0.0f);
    }
}

// ---------------------------------------------------------------------------
// Kernel 2: one CTA per TWO scenarios; 150 projected-subgradient iterations.
// Thread t handles observation t for both scenarios (shared ep_r registers).
// ---------------------------------------------------------------------------
__global__ __launch_bounds__(256, 1)
void solver_kernel(const float* __restrict__ yhat_all,
                   const float* __restrict__ delta_p,
                   const float* __restrict__ gamma_p,
                   float* __restrict__ zout) {
    extern __shared__ char smem_raw[];
    SolverSmem* S = reinterpret_cast<SolverSmem*>(smem_raw);

    const int tid = threadIdx.x;
    const int sA = blockIdx.x * 2;
    const int sB = sA + 1;
    const float delta = *delta_p;
    const float gamma = *gamma_p;

    for (int idx = tid; idx < N_Y * N_OBS; idx += 256) {
        const int j = idx >> 8;
        const int t = idx & 255;
        S->epT[j * EPT_STRIDE + t] = g_epT[idx];
    }
    if (tid < N_Y) {
        S->zA[tid] = 1.0f / (float)N_Y;
        S->zB[tid] = 1.0f / (float)N_Y;
        S->yhA[tid] = yhat_all[sA * N_Y + tid];
        S->yhB[tid] = yhat_all[sB * N_Y + tid];
    }
    if (tid == 0)  { S->cA = 0.0f; S->etaA = 0.0f; S->lamA = 0.1f; }
    if (tid == 32) { S->cB = 0.0f; S->etaB = 0.0f; S->lamB = 0.1f; }
    __syncthreads();

    // Cache ep row t in registers: ep[t][j]
    float ep_r[N_Y];
#pragma unroll
    for (int j = 0; j < N_Y; j++) ep_r[j] = S->epT[j * EPT_STRIDE + tid];

    for (int k = 0; k < NITERS; k++) {
        const float lr = 0.05f / sqrtf(1.0f + (float)k);
        const float cA = S->cA, etaA = S->etaA, lamA = S->lamA;
        const float cB = S->cB, etaB = S->etaB, lamB = S->lamB;

        // ---- Phase A: r_t for both scenarios (register FMAs, z broadcast) ----
        float rA = -cA, rB = -cB;
        const float4* zA4 = reinterpret_cast<const float4*>(S->zA);
        const float4* zB4 = reinterpret_cast<const float4*>(S->zB);
#pragma unroll
        for (int q = 0; q < N_Y / 4; q++) {
            const float4 za = zA4[q];
            const float4 zb = zB4[q];
            rA += ep_r[4*q+0] * za.x; rB += ep_r[4*q+0] * zb.x;
            rA += ep_r[4*q+1] * za.y; rB += ep_r[4*q+1] * zb.y;
            rA += ep_r[4*q+2] * za.z; rB += ep_r[4*q+2] * zb.z;
            rA += ep_r[4*q+3] * za.w; rB += ep_r[4*q+3] * zb.w;
        }

        const float aA = rA * rA - etaA;
        const float aB = rB * rB - etaB;
        float IA = (aA > -lamA) ? 1.0f : ((aA < -lamA) ? 0.0f : 0.5f);
        float IB = (aB > -lamB) ? 1.0f : ((aB < -lamB) ? 0.0f : 0.5f);
        const float wAv = IA * 2.0f * rA * (1.0f / (float)N_OBS);
        const float wBv = IB * 2.0f * rB * (1.0f / (float)N_OBS);
        S->wA[tid] = wAv;
        S->wB[tid] = wBv;

        float sIA = IA, sWA = wAv, sIB = IB, sWB = wBv;
#pragma unroll
        for (int off = 16; off > 0; off >>= 1) {
            sIA += __shfl_down_sync(0xffffffffu, sIA, off);
            sWA += __shfl_down_sync(0xffffffffu, sWA, off);
            sIB += __shfl_down_sync(0xffffffffu, sIB, off);
            sWB += __shfl_down_sync(0xffffffffu, sWB, off);
        }
        if ((tid & 31) == 0) {
            const int wd = tid >> 5;
            S->redIA[wd] = sIA; S->redWA[wd] = sWA;
            S->redIB[wd] = sIB; S->redWB[wd] = sWB;
        }
        __syncthreads();   // B1: w, reductions visible

        // ---- Scalar updates (overlap with Phase B) ----
        if (tid == 0) {
            float SI = 0.0f, SW = 0.0f;
#pragma unroll
            for (int i = 0; i < 8; i++) { SI += S->redIA[i]; SW += S->redWA[i]; }
            S->cA   = cA + lr * SW;                                  // g_c = -SW
            S->etaA = etaA - lr * (1.0f - SI * (1.0f / (float)N_OBS));
            S->lamA = fmaxf(lamA - lr * (delta - 1.0f + SI * (1.0f / (float)N_OBS)), 0.0f);
        }
        if (tid == 32) {
            float SI = 0.0f, SW = 0.0f;
#pragma unroll
            for (int i = 0; i < 8; i++) { SI += S->redIB[i]; SW += S->redWB[i]; }
            S->cB   = cB + lr * SW;
            S->etaB = etaB - lr * (1.0f - SI * (1.0f / (float)N_OBS));
            S->lamB = fmaxf(lamB - lr * (delta - 1.0f + SI * (1.0f / (float)N_OBS)), 0.0f);
        }

        // ---- Phase B: g_z[j] = sum_t w_t * epT[j][t], both scenarios ----
        {
            const int j = tid & 127;
            const int tbase = (tid >> 7) << 7;   // 0 or 128
            const float4* row = reinterpret_cast<const float4*>(&S->epT[j * EPT_STRIDE + tbase]);
            const float4* a4 = reinterpret_cast<const float4*>(&S->wA[tbase]);
            const float4* b4 = reinterpret_cast<const float4*>(&S->wB[tbase]);
            float accA = 0.0f, accB = 0.0f;
#pragma unroll
            for (int q = 0; q < 32; q++) {
                const float4 e  = row[q];
                const float4 wa = a4[q];
                const float4 wb = b4[q];
                accA += e.x * wa.x + e.y * wa.y + e.z * wa.z + e.w * wa.w;
                accB += e.x * wb.x + e.y * wb.y + e.z * wb.z + e.w * wb.w;
            }
            S->partA[tid] = accA;
            S->partB[tid] = accB;
        }
        __syncthreads();   // B2

        if (tid < 128) {
            const float gz = S->partA[tid] + S->partA[tid + 128] - gamma * S->yhA[tid];
            S->vA[tid] = S->zA[tid] - lr * gz;
        } else {
            const int j2 = tid - 128;
            const float gz = S->partB[j2] + S->partB[j2 + 128] - gamma * S->yhB[j2];
            S->vB[j2] = S->zB[j2] - lr * gz;
        }
        __syncthreads();   // B3

        const int wid = tid >> 5;
        if (wid == 0)      project_warp(S->vA, S->zA);
        else if (wid == 1) project_warp(S->vB, S->zB);
        __syncthreads();   // B4
    }

    if (tid < 128) {
        zout[sA * N_Y + tid] = S->zA[tid];
    } else {
        zout[sB * N_Y + (tid - 128)] = S->zB[tid - 128];
    }
}

// ---------------------------------------------------------------------------
extern "C" void kernel_launch(void* const* d_in, const int* in_sizes, int n_in,
                              void* d_out, int out_size) {
    const float* X     = (const float*)d_in[0];
    const float* Y     = (const float*)d_in[1];
    const float* W     = (const float*)d_in[2];
    const float* b     = (const float*)d_in[3];
    const float* delta = (const float*)d_in[4];
    const float* gamma = (const float*)d_in[5];

    float* out = (float*)d_out;
    float* zout = out;
    float* yhat;
    if (out_size >= 2 * N_OBS * N_Y) {
        yhat = out + N_OBS * N_Y;
    } else {
        void* p = nullptr;
        cudaGetSymbolAddress(&p, g_yhat_fallback);
        yhat = (float*)p;
    }

    static const size_t smem_bytes = sizeof(SolverSmem);
    cudaFuncSetAttribute(solver_kernel,
                         cudaFuncAttributeMaxDynamicSharedMemorySize,
                         (int)smem_bytes);

    prep_kernel<<<N_OBS, N_Y>>>(X, Y, W, b, yhat);
    solver_kernel<<<N_OBS / 2, 256, smem_bytes>>>(yhat, delta, gamma, zout);
}